// round 1
// baseline (speedup 1.0000x reference)
#include <cuda_runtime.h>
#include <cstdint>

// Problem constants (fixed by the reference)
#define N_NODES 1000000
#define N_EDGES 5000000
#define N_LABEL 2000000
#define FDIM    16

// Scratch (device globals — no allocation allowed)
__device__ float g_dinv[N_NODES];              // deg accumulator, then rsqrt(deg)
__device__ float g_hw  [N_NODES * FDIM];       // h @ W (message source)
__device__ float g_agg [N_NODES * FDIM];       // aggregation accumulator

// ---------------------------------------------------------------------------
// K0: deg init = 1 (self loop)
__global__ void k_init_deg() {
    int i = blockIdx.x * blockDim.x + threadIdx.x;
    if (i < N_NODES) g_dinv[i] = 1.0f;
}

// K1: deg[dst] += 1 per edge
__global__ void k_degree(const int* __restrict__ dst) {
    int e = blockIdx.x * blockDim.x + threadIdx.x;
    if (e < N_EDGES) atomicAdd(&g_dinv[dst[e]], 1.0f);
}

// K2: dinv = rsqrt(deg)  (deg >= 1 always, no guard needed)
__global__ void k_rsqrt() {
    int i = blockIdx.x * blockDim.x + threadIdx.x;
    if (i < N_NODES) g_dinv[i] = rsqrtf(g_dinv[i]);
}

// ---------------------------------------------------------------------------
// K3: layer-1 matmul + self-loop init.
//   hw[i]  = embed[x[i]] @ W1
//   agg[i] = hw[i] * dinv[i]^2
__global__ void k_mm1(const int* __restrict__ x,
                      const float* __restrict__ embed,
                      const float* __restrict__ W1) {
    __shared__ float Ws[FDIM][FDIM];
    if (threadIdx.x < 256) {
        int k = threadIdx.x >> 4, j = threadIdx.x & 15;
        Ws[k][j] = W1[threadIdx.x];
    }
    __syncthreads();

    int i = blockIdx.x * blockDim.x + threadIdx.x;
    if (i >= N_NODES) return;

    const float4* rp = (const float4*)(embed + (size_t)x[i] * FDIM);
    float4 r0 = rp[0], r1 = rp[1], r2 = rp[2], r3 = rp[3];
    float row[FDIM] = {r0.x,r0.y,r0.z,r0.w, r1.x,r1.y,r1.z,r1.w,
                       r2.x,r2.y,r2.z,r2.w, r3.x,r3.y,r3.z,r3.w};
    float out[FDIM];
    #pragma unroll
    for (int j = 0; j < FDIM; j++) {
        float acc = 0.f;
        #pragma unroll
        for (int k = 0; k < FDIM; k++) acc = fmaf(row[k], Ws[k][j], acc);
        out[j] = acc;
    }
    float dv = g_dinv[i];
    float s  = dv * dv;
    float4* hw  = (float4*)(g_hw  + (size_t)i * FDIM);
    float4* ag  = (float4*)(g_agg + (size_t)i * FDIM);
    #pragma unroll
    for (int q = 0; q < 4; q++) {
        float4 v = make_float4(out[4*q], out[4*q+1], out[4*q+2], out[4*q+3]);
        hw[q] = v;
        ag[q] = make_float4(v.x*s, v.y*s, v.z*s, v.w*s);
    }
}

// ---------------------------------------------------------------------------
// red.global.add.v4.f32 (sm_90+): 4 fewer atomic issues per 64B
__device__ __forceinline__ void red_add_v4(float* p, float4 v) {
    asm volatile("red.global.add.v4.f32 [%0], {%1,%2,%3,%4};"
                 :: "l"(p), "f"(v.x), "f"(v.y), "f"(v.z), "f"(v.w) : "memory");
}

// K4/K7: edge aggregation: agg[dst] += hw[src] * dinv[src]*dinv[dst]
__global__ void k_edge_agg(const int* __restrict__ src,
                           const int* __restrict__ dst) {
    int e = blockIdx.x * blockDim.x + threadIdx.x;
    if (e >= N_EDGES) return;
    int s = src[e], d = dst[e];
    float norm = g_dinv[s] * g_dinv[d];
    const float4* sp = (const float4*)(g_hw + (size_t)s * FDIM);
    float*        dp = g_agg + (size_t)d * FDIM;
    #pragma unroll
    for (int q = 0; q < 4; q++) {
        float4 v = sp[q];
        red_add_v4(dp + 4*q,
                   make_float4(v.x*norm, v.y*norm, v.z*norm, v.w*norm));
    }
}

// ---------------------------------------------------------------------------
// K6: layer-2 matmul with fused relu(agg1 + b1), + self-loop init.
//   h1   = relu(agg[i] + b1)          (reads agg in place)
//   hw[i]  = h1 @ W2                  (overwrites layer-1 hw — safe, agg1 done)
//   agg[i] = hw[i] * dinv[i]^2        (overwrites own row — per-thread private)
__global__ void k_mm2(const float* __restrict__ W2,
                      const float* __restrict__ b1) {
    __shared__ float Ws[FDIM][FDIM];
    __shared__ float bs[FDIM];
    if (threadIdx.x < 256) {
        int k = threadIdx.x >> 4, j = threadIdx.x & 15;
        Ws[k][j] = W2[threadIdx.x];
        if (threadIdx.x < FDIM) bs[threadIdx.x] = b1[threadIdx.x];
    }
    __syncthreads();

    int i = blockIdx.x * blockDim.x + threadIdx.x;
    if (i >= N_NODES) return;

    float row[FDIM];
    const float4* ap = (const float4*)(g_agg + (size_t)i * FDIM);
    #pragma unroll
    for (int q = 0; q < 4; q++) {
        float4 v = ap[q];
        row[4*q+0] = fmaxf(v.x + bs[4*q+0], 0.f);
        row[4*q+1] = fmaxf(v.y + bs[4*q+1], 0.f);
        row[4*q+2] = fmaxf(v.z + bs[4*q+2], 0.f);
        row[4*q+3] = fmaxf(v.w + bs[4*q+3], 0.f);
    }
    float out[FDIM];
    #pragma unroll
    for (int j = 0; j < FDIM; j++) {
        float acc = 0.f;
        #pragma unroll
        for (int k = 0; k < FDIM; k++) acc = fmaf(row[k], Ws[k][j], acc);
        out[j] = acc;
    }
    float dv = g_dinv[i];
    float s  = dv * dv;
    float4* hw = (float4*)(g_hw  + (size_t)i * FDIM);
    float4* ag = (float4*)(g_agg + (size_t)i * FDIM);
    #pragma unroll
    for (int q = 0; q < 4; q++) {
        float4 v = make_float4(out[4*q], out[4*q+1], out[4*q+2], out[4*q+3]);
        hw[q] = v;
        ag[q] = make_float4(v.x*s, v.y*s, v.z*s, v.w*s);
    }
}

// ---------------------------------------------------------------------------
// K8: link prediction.
//   z = agg + b2;  out[e] = dot(z[a], fw[0:16]) + dot(z[b], fw[16:32]) + fc_b
// The b2 contribution is a constant C = fc_b + sum_j b2[j]*(fw[j]+fw[16+j]).
__global__ void k_predict(const int* __restrict__ la,
                          const int* __restrict__ lb,
                          const float* __restrict__ fc_w,
                          const float* __restrict__ fc_b,
                          const float* __restrict__ b2,
                          float* __restrict__ out) {
    __shared__ float fw[32];
    __shared__ float b2s[FDIM];
    __shared__ float fb;
    if (threadIdx.x < 32) fw[threadIdx.x] = fc_w[threadIdx.x];
    if (threadIdx.x < FDIM) b2s[threadIdx.x] = b2[threadIdx.x];
    if (threadIdx.x == 0) fb = fc_b[0];
    __syncthreads();

    int e = blockIdx.x * blockDim.x + threadIdx.x;
    if (e >= N_LABEL) return;

    float C = fb;
    #pragma unroll
    for (int j = 0; j < FDIM; j++) C = fmaf(b2s[j], fw[j] + fw[FDIM + j], C);

    int a = la[e], b = lb[e];
    const float4* za = (const float4*)(g_agg + (size_t)a * FDIM);
    const float4* zb = (const float4*)(g_agg + (size_t)b * FDIM);
    float acc = C;
    #pragma unroll
    for (int q = 0; q < 4; q++) {
        float4 va = za[q];
        acc = fmaf(va.x, fw[4*q+0], acc);
        acc = fmaf(va.y, fw[4*q+1], acc);
        acc = fmaf(va.z, fw[4*q+2], acc);
        acc = fmaf(va.w, fw[4*q+3], acc);
    }
    #pragma unroll
    for (int q = 0; q < 4; q++) {
        float4 vb = zb[q];
        acc = fmaf(vb.x, fw[FDIM+4*q+0], acc);
        acc = fmaf(vb.y, fw[FDIM+4*q+1], acc);
        acc = fmaf(vb.z, fw[FDIM+4*q+2], acc);
        acc = fmaf(vb.w, fw[FDIM+4*q+3], acc);
    }
    out[e] = acc;
}

// ---------------------------------------------------------------------------
extern "C" void kernel_launch(void* const* d_in, const int* in_sizes, int n_in,
                              void* d_out, int out_size) {
    const int*   x     = (const int*)  d_in[0];
    const int*   ei    = (const int*)  d_in[1];   // [2, E] row-major
    const int*   eli   = (const int*)  d_in[2];   // [2, EL]
    const float* embed = (const float*)d_in[3];
    const float* W1    = (const float*)d_in[4];
    const float* b1    = (const float*)d_in[5];
    const float* W2    = (const float*)d_in[6];
    const float* b2    = (const float*)d_in[7];
    const float* fc_w  = (const float*)d_in[8];
    const float* fc_b  = (const float*)d_in[9];
    float*       out   = (float*)d_out;

    const int* e_src = ei;
    const int* e_dst = ei + N_EDGES;
    const int* l_a   = eli;
    const int* l_b   = eli + N_LABEL;

    const int TB = 256;
    int gN  = (N_NODES + TB - 1) / TB;
    int gE  = (N_EDGES + TB - 1) / TB;
    int gL  = (N_LABEL + TB - 1) / TB;

    k_init_deg<<<gN, TB>>>();
    k_degree  <<<gE, TB>>>(e_dst);
    k_rsqrt   <<<gN, TB>>>();
    k_mm1     <<<gN, TB>>>(x, embed, W1);
    k_edge_agg<<<gE, TB>>>(e_src, e_dst);
    k_mm2     <<<gN, TB>>>(W2, b1);
    k_edge_agg<<<gE, TB>>>(e_src, e_dst);
    k_predict <<<gL, TB>>>(l_a, l_b, fc_w, fc_b, b2, out);
}

// round 2
// speedup vs baseline: 1.3219x; 1.3219x over previous
#include <cuda_runtime.h>
#include <cuda_fp16.h>
#include <cstdint>

#define N_NODES 1000000
#define N_EDGES 5000000
#define N_LABEL 2000000
#define FDIM    16

// Scratch (device globals — no allocation allowed)
__device__ float   g_dinv[N_NODES];            // deg accumulator, then rsqrt(deg)
__device__ __half2 g_msg [N_NODES * 8];        // fp16 messages: hw[i]*dinv[i], 32B/row
__device__ float   g_agg [N_NODES * FDIM];     // fp32 aggregation accumulator

// ---------------------------------------------------------------------------
__global__ void k_init_deg() {
    int i = blockIdx.x * blockDim.x + threadIdx.x;
    if (i < N_NODES) g_dinv[i] = 1.0f;   // self loop
}

__global__ void k_degree(const int* __restrict__ dst) {
    int e = blockIdx.x * blockDim.x + threadIdx.x;
    if (e < N_EDGES) atomicAdd(&g_dinv[dst[e]], 1.0f);
}

__global__ void k_rsqrt() {
    int i = blockIdx.x * blockDim.x + threadIdx.x;
    if (i < N_NODES) g_dinv[i] = rsqrtf(g_dinv[i]);
}

// ---------------------------------------------------------------------------
// Write msg (half) + agg init (fp32), both = out * dinv[i].
__device__ __forceinline__ void store_msg_agg(int i, const float* out, float dv) {
    float t[FDIM];
    #pragma unroll
    for (int k = 0; k < FDIM; k++) t[k] = out[k] * dv;

    __half2* mp = g_msg + (size_t)i * 8;
    uint4 m0, m1;
    __half2 h[8];
    #pragma unroll
    for (int q = 0; q < 8; q++)
        h[q] = __floats2half2_rn(t[2*q], t[2*q+1]);
    m0 = make_uint4(*(uint32_t*)&h[0], *(uint32_t*)&h[1], *(uint32_t*)&h[2], *(uint32_t*)&h[3]);
    m1 = make_uint4(*(uint32_t*)&h[4], *(uint32_t*)&h[5], *(uint32_t*)&h[6], *(uint32_t*)&h[7]);
    ((uint4*)mp)[0] = m0;
    ((uint4*)mp)[1] = m1;

    float4* ap = (float4*)(g_agg + (size_t)i * FDIM);
    #pragma unroll
    for (int q = 0; q < 4; q++)
        ap[q] = make_float4(t[4*q], t[4*q+1], t[4*q+2], t[4*q+3]);
}

// K3: layer-1 matmul:  out = embed[x[i]] @ W1;  msg/agg init.
__global__ void k_mm1(const int* __restrict__ x,
                      const float* __restrict__ embed,
                      const float* __restrict__ W1) {
    __shared__ float Ws[FDIM][FDIM];
    if (threadIdx.x < 256) {
        int k = threadIdx.x >> 4, j = threadIdx.x & 15;
        Ws[k][j] = W1[threadIdx.x];
    }
    __syncthreads();

    int i = blockIdx.x * blockDim.x + threadIdx.x;
    if (i >= N_NODES) return;

    const float4* rp = (const float4*)(embed + (size_t)x[i] * FDIM);
    float4 r0 = rp[0], r1 = rp[1], r2 = rp[2], r3 = rp[3];
    float row[FDIM] = {r0.x,r0.y,r0.z,r0.w, r1.x,r1.y,r1.z,r1.w,
                       r2.x,r2.y,r2.z,r2.w, r3.x,r3.y,r3.z,r3.w};
    float out[FDIM];
    #pragma unroll
    for (int j = 0; j < FDIM; j++) {
        float acc = 0.f;
        #pragma unroll
        for (int k = 0; k < FDIM; k++) acc = fmaf(row[k], Ws[k][j], acc);
        out[j] = acc;
    }
    store_msg_agg(i, out, g_dinv[i]);
}

// ---------------------------------------------------------------------------
__device__ __forceinline__ void red_add_v4(float* p, float4 v) {
    asm volatile("red.global.add.v4.f32 [%0], {%1,%2,%3,%4};"
                 :: "l"(p), "f"(v.x), "f"(v.y), "f"(v.z), "f"(v.w) : "memory");
}

// K4/K7: edge aggregation:  agg[dst] += msg[src]   (scale deferred)
__global__ void k_edge_agg(const int* __restrict__ src,
                           const int* __restrict__ dst) {
    int e = blockIdx.x * blockDim.x + threadIdx.x;
    if (e >= N_EDGES) return;
    int s = src[e], d = dst[e];

    const uint4* sp = (const uint4*)(g_msg + (size_t)s * 8);
    uint4 m0 = sp[0], m1 = sp[1];
    float* dp = g_agg + (size_t)d * FDIM;

    float2 f0 = __half22float2(*(__half2*)&m0.x);
    float2 f1 = __half22float2(*(__half2*)&m0.y);
    float2 f2 = __half22float2(*(__half2*)&m0.z);
    float2 f3 = __half22float2(*(__half2*)&m0.w);
    red_add_v4(dp + 0, make_float4(f0.x, f0.y, f1.x, f1.y));
    red_add_v4(dp + 4, make_float4(f2.x, f2.y, f3.x, f3.y));

    float2 f4 = __half22float2(*(__half2*)&m1.x);
    float2 f5 = __half22float2(*(__half2*)&m1.y);
    float2 f6 = __half22float2(*(__half2*)&m1.z);
    float2 f7 = __half22float2(*(__half2*)&m1.w);
    red_add_v4(dp + 8,  make_float4(f4.x, f4.y, f5.x, f5.y));
    red_add_v4(dp + 12, make_float4(f6.x, f6.y, f7.x, f7.y));
}

// ---------------------------------------------------------------------------
// K6: layer-2 matmul.
//   h1  = relu(dinv[i]*agg[i] + b1)   (applies the deferred dst-scale)
//   out = h1 @ W2;  msg/agg re-init with out*dinv[i].
__global__ void k_mm2(const float* __restrict__ W2,
                      const float* __restrict__ b1) {
    __shared__ float Ws[FDIM][FDIM];
    __shared__ float bs[FDIM];
    if (threadIdx.x < 256) {
        int k = threadIdx.x >> 4, j = threadIdx.x & 15;
        Ws[k][j] = W2[threadIdx.x];
        if (threadIdx.x < FDIM) bs[threadIdx.x] = b1[threadIdx.x];
    }
    __syncthreads();

    int i = blockIdx.x * blockDim.x + threadIdx.x;
    if (i >= N_NODES) return;

    float dv = g_dinv[i];
    float row[FDIM];
    const float4* ap = (const float4*)(g_agg + (size_t)i * FDIM);
    #pragma unroll
    for (int q = 0; q < 4; q++) {
        float4 v = ap[q];
        row[4*q+0] = fmaxf(fmaf(dv, v.x, bs[4*q+0]), 0.f);
        row[4*q+1] = fmaxf(fmaf(dv, v.y, bs[4*q+1]), 0.f);
        row[4*q+2] = fmaxf(fmaf(dv, v.z, bs[4*q+2]), 0.f);
        row[4*q+3] = fmaxf(fmaf(dv, v.w, bs[4*q+3]), 0.f);
    }
    float out[FDIM];
    #pragma unroll
    for (int j = 0; j < FDIM; j++) {
        float acc = 0.f;
        #pragma unroll
        for (int k = 0; k < FDIM; k++) acc = fmaf(row[k], Ws[k][j], acc);
        out[j] = acc;
    }
    store_msg_agg(i, out, dv);
}

// ---------------------------------------------------------------------------
// K8: link prediction.
//   z[i] = dinv[i]*agg[i] + b2   (deferred scale applied here)
//   out[e] = dot(z[a], fw[0:16]) + dot(z[b], fw[16:32]) + fc_b
//          = dinv[a]*dot(agg[a],fwA) + dinv[b]*dot(agg[b],fwB) + C
__global__ void k_predict(const int* __restrict__ la,
                          const int* __restrict__ lb,
                          const float* __restrict__ fc_w,
                          const float* __restrict__ fc_b,
                          const float* __restrict__ b2,
                          float* __restrict__ out) {
    __shared__ float fw[32];
    __shared__ float b2s[FDIM];
    __shared__ float fb;
    if (threadIdx.x < 32) fw[threadIdx.x] = fc_w[threadIdx.x];
    if (threadIdx.x < FDIM) b2s[threadIdx.x] = b2[threadIdx.x];
    if (threadIdx.x == 0) fb = fc_b[0];
    __syncthreads();

    int e = blockIdx.x * blockDim.x + threadIdx.x;
    if (e >= N_LABEL) return;

    float C = fb;
    #pragma unroll
    for (int j = 0; j < FDIM; j++) C = fmaf(b2s[j], fw[j] + fw[FDIM + j], C);

    int a = la[e], b = lb[e];
    float dva = g_dinv[a], dvb = g_dinv[b];
    const float4* za = (const float4*)(g_agg + (size_t)a * FDIM);
    const float4* zb = (const float4*)(g_agg + (size_t)b * FDIM);

    float accA = 0.f, accB = 0.f;
    #pragma unroll
    for (int q = 0; q < 4; q++) {
        float4 va = za[q];
        accA = fmaf(va.x, fw[4*q+0], accA);
        accA = fmaf(va.y, fw[4*q+1], accA);
        accA = fmaf(va.z, fw[4*q+2], accA);
        accA = fmaf(va.w, fw[4*q+3], accA);
    }
    #pragma unroll
    for (int q = 0; q < 4; q++) {
        float4 vb = zb[q];
        accB = fmaf(vb.x, fw[FDIM+4*q+0], accB);
        accB = fmaf(vb.y, fw[FDIM+4*q+1], accB);
        accB = fmaf(vb.z, fw[FDIM+4*q+2], accB);
        accB = fmaf(vb.w, fw[FDIM+4*q+3], accB);
    }
    out[e] = fmaf(dva, accA, fmaf(dvb, accB, C));
}

// ---------------------------------------------------------------------------
extern "C" void kernel_launch(void* const* d_in, const int* in_sizes, int n_in,
                              void* d_out, int out_size) {
    const int*   x     = (const int*)  d_in[0];
    const int*   ei    = (const int*)  d_in[1];   // [2, E] row-major
    const int*   eli   = (const int*)  d_in[2];   // [2, EL]
    const float* embed = (const float*)d_in[3];
    const float* W1    = (const float*)d_in[4];
    const float* b1    = (const float*)d_in[5];
    const float* W2    = (const float*)d_in[6];
    const float* b2    = (const float*)d_in[7];
    const float* fc_w  = (const float*)d_in[8];
    const float* fc_b  = (const float*)d_in[9];
    float*       out   = (float*)d_out;

    const int* e_src = ei;
    const int* e_dst = ei + N_EDGES;
    const int* l_a   = eli;
    const int* l_b   = eli + N_LABEL;

    const int TB = 256;
    int gN = (N_NODES + TB - 1) / TB;
    int gE = (N_EDGES + TB - 1) / TB;
    int gL = (N_LABEL + TB - 1) / TB;

    k_init_deg<<<gN, TB>>>();
    k_degree  <<<gE, TB>>>(e_dst);
    k_rsqrt   <<<gN, TB>>>();
    k_mm1     <<<gN, TB>>>(x, embed, W1);
    k_edge_agg<<<gE, TB>>>(e_src, e_dst);
    k_mm2     <<<gN, TB>>>(W2, b1);
    k_edge_agg<<<gE, TB>>>(e_src, e_dst);
    k_predict <<<gL, TB>>>(l_a, l_b, fc_w, fc_b, b2, out);
}

// round 3
// speedup vs baseline: 1.5626x; 1.1821x over previous
#include <cuda_runtime.h>
#include <cuda_fp16.h>
#include <cstdint>

#define N_NODES 1000000
#define N_EDGES 5000000
#define N_LABEL 2000000
#define FDIM    16

#define SCAN_CHUNK 2048
#define NB ((N_NODES + SCAN_CHUNK - 1) / SCAN_CHUNK)   // 489

// Scratch (device globals — allocation is forbidden)
__device__ int      g_deg [N_NODES];
__device__ int      g_off [N_NODES + 1];
__device__ int      g_cur [N_NODES];
__device__ int      g_csr [N_EDGES];
__device__ int      g_bsum[NB];
__device__ float    g_dinv[N_NODES];
__device__ unsigned g_msg1[N_NODES * 8];   // layer-1 messages, half2-packed
__device__ unsigned g_msg2[N_NODES * 8];   // layer-2 messages, half2-packed
__device__ float    g_z   [N_NODES * FDIM];// final node embeddings (z)

// ---------------------------------------------------------------------------
__global__ void k_zero_deg() {
    int i = blockIdx.x * blockDim.x + threadIdx.x;
    if (i < N_NODES) g_deg[i] = 0;
}

__global__ void k_count(const int* __restrict__ dst) {
    int e = blockIdx.x * blockDim.x + threadIdx.x;
    if (e < N_EDGES) atomicAdd(&g_deg[dst[e]], 1);
}

// ---------------------------------------------------------------------------
// 3-phase exclusive scan of g_deg into g_off.
__global__ void k_scan1() {
    __shared__ int s[256];
    int b = blockIdx.x, t = threadIdx.x;
    int base = b * SCAN_CHUNK + t * 8;
    int v[8], sum = 0;
    #pragma unroll
    for (int q = 0; q < 8; q++) {
        int idx = base + q;
        int d = (idx < N_NODES) ? g_deg[idx] : 0;
        v[q] = sum; sum += d;
    }
    s[t] = sum; __syncthreads();
    for (int o = 1; o < 256; o <<= 1) {
        int x = (t >= o) ? s[t - o] : 0;
        __syncthreads();
        s[t] += x;
        __syncthreads();
    }
    int excl = (t > 0) ? s[t - 1] : 0;
    #pragma unroll
    for (int q = 0; q < 8; q++) {
        int idx = base + q;
        if (idx < N_NODES) g_off[idx] = v[q] + excl;
    }
    if (t == 255) g_bsum[b] = s[255];
}

__global__ void k_scan2() {   // one block, 512 threads, scans NB block sums
    __shared__ int s[512];
    int t = threadIdx.x;
    s[t] = (t < NB) ? g_bsum[t] : 0;
    __syncthreads();
    for (int o = 1; o < 512; o <<= 1) {
        int x = (t >= o) ? s[t - o] : 0;
        __syncthreads();
        s[t] += x;
        __syncthreads();
    }
    if (t < NB) g_bsum[t] = (t > 0) ? s[t - 1] : 0;   // exclusive
}

// add block offsets; also finalize dinv and init fill cursors
__global__ void k_scan3() {
    int i = blockIdx.x * blockDim.x + threadIdx.x;
    if (i < N_NODES) {
        int o = g_off[i] + g_bsum[i >> 11];
        g_off[i] = o;
        g_cur[i] = o;
        g_dinv[i] = rsqrtf((float)(g_deg[i] + 1));   // +1 self loop
    }
    if (i == 0) g_off[N_NODES] = N_EDGES;
}

__global__ void k_fill(const int* __restrict__ src, const int* __restrict__ dst) {
    int e = blockIdx.x * blockDim.x + threadIdx.x;
    if (e >= N_EDGES) return;
    int pos = atomicAdd(&g_cur[dst[e]], 1);
    g_csr[pos] = src[e];
}

// ---------------------------------------------------------------------------
// K-mm1: msg1[i] = (embed[x[i]] @ W1) * dinv[i]  (half2-packed, 32 B/node)
__global__ void k_mm1(const int* __restrict__ x,
                      const float* __restrict__ embed,
                      const float* __restrict__ W1) {
    __shared__ float Ws[FDIM][FDIM];
    if (threadIdx.x < 256) {
        int k = threadIdx.x >> 4, j = threadIdx.x & 15;
        Ws[k][j] = W1[threadIdx.x];
    }
    __syncthreads();

    int i = blockIdx.x * blockDim.x + threadIdx.x;
    if (i >= N_NODES) return;

    const float4* rp = (const float4*)(embed + (size_t)x[i] * FDIM);
    float4 r0 = rp[0], r1 = rp[1], r2 = rp[2], r3 = rp[3];
    float row[FDIM] = {r0.x,r0.y,r0.z,r0.w, r1.x,r1.y,r1.z,r1.w,
                       r2.x,r2.y,r2.z,r2.w, r3.x,r3.y,r3.z,r3.w};
    float dv = g_dinv[i];
    float out[FDIM];
    #pragma unroll
    for (int j = 0; j < FDIM; j++) {
        float acc = 0.f;
        #pragma unroll
        for (int k = 0; k < FDIM; k++) acc = fmaf(row[k], Ws[k][j], acc);
        out[j] = acc * dv;
    }
    __half2 h[8];
    #pragma unroll
    for (int q = 0; q < 8; q++) h[q] = __floats2half2_rn(out[2*q], out[2*q+1]);
    uint4* mp = (uint4*)(g_msg1 + (size_t)i * 8);
    mp[0] = make_uint4(*(unsigned*)&h[0], *(unsigned*)&h[1], *(unsigned*)&h[2], *(unsigned*)&h[3]);
    mp[1] = make_uint4(*(unsigned*)&h[4], *(unsigned*)&h[5], *(unsigned*)&h[6], *(unsigned*)&h[7]);
}

// ---------------------------------------------------------------------------
// K-gather1 fused with layer-2 matmul:
//   acc  = msg1[i] + Σ_{s in CSR(i)} msg1[s]        (fp32 regs, 8 thr/node)
//   h1   = relu(dinv[i]*acc + b1)
//   msg2[i] = (h1 @ W2) * dinv[i]                   (half2-packed)
// Grid is exact: 1e6 nodes / 32 per block — no tail, full-warp shuffles safe.
__global__ void k_gather_mm2(const float* __restrict__ W2,
                             const float* __restrict__ b1) {
    __shared__ float Ws[FDIM][FDIM];
    __shared__ float bs[FDIM];
    if (threadIdx.x < 256) {
        int k = threadIdx.x >> 4, j = threadIdx.x & 15;
        Ws[k][j] = W2[threadIdx.x];
        if (threadIdx.x < FDIM) bs[threadIdx.x] = b1[threadIdx.x];
    }
    __syncthreads();

    int node = blockIdx.x * 32 + (threadIdx.x >> 3);
    int t    = threadIdx.x & 7;
    int lane = threadIdx.x & 31;

    int o0 = g_off[node], o1 = g_off[node + 1];

    unsigned mself = g_msg1[(size_t)node * 8 + t];
    float2 acc = __half22float2(*(__half2*)&mself);
    for (int j = o0; j < o1; j++) {
        int s = g_csr[j];
        unsigned m = g_msg1[(size_t)s * 8 + t];
        float2 f = __half22float2(*(__half2*)&m);
        acc.x += f.x; acc.y += f.y;
    }

    float dv = g_dinv[node];
    float h0 = fmaxf(fmaf(dv, acc.x, bs[2*t]),     0.f);
    float h1 = fmaxf(fmaf(dv, acc.y, bs[2*t + 1]), 0.f);

    float o[2] = {0.f, 0.f};
    int gbase = lane & ~7;
    #pragma unroll
    for (int k = 0; k < FDIM; k++) {
        float hk = __shfl_sync(0xFFFFFFFFu, (k & 1) ? h1 : h0, gbase + (k >> 1));
        o[0] = fmaf(hk, Ws[k][2*t],     o[0]);
        o[1] = fmaf(hk, Ws[k][2*t + 1], o[1]);
    }
    __half2 hh = __floats2half2_rn(o[0] * dv, o[1] * dv);
    g_msg2[(size_t)node * 8 + t] = *(unsigned*)&hh;
}

// ---------------------------------------------------------------------------
// K-gather2: z[i] = dinv[i] * (msg2[i] + Σ msg2[s]) + b2   (fp32, 64 B/node)
__global__ void k_gather_z(const float* __restrict__ b2) {
    __shared__ float bs[FDIM];
    if (threadIdx.x < FDIM) bs[threadIdx.x] = b2[threadIdx.x];
    __syncthreads();

    int node = blockIdx.x * 32 + (threadIdx.x >> 3);
    int t    = threadIdx.x & 7;

    int o0 = g_off[node], o1 = g_off[node + 1];

    unsigned mself = g_msg2[(size_t)node * 8 + t];
    float2 acc = __half22float2(*(__half2*)&mself);
    for (int j = o0; j < o1; j++) {
        int s = g_csr[j];
        unsigned m = g_msg2[(size_t)s * 8 + t];
        float2 f = __half22float2(*(__half2*)&m);
        acc.x += f.x; acc.y += f.y;
    }
    float dv = g_dinv[node];
    float2 zv = make_float2(fmaf(dv, acc.x, bs[2*t]),
                            fmaf(dv, acc.y, bs[2*t + 1]));
    *(float2*)(g_z + (size_t)node * FDIM + 2*t) = zv;
}

// ---------------------------------------------------------------------------
// K-predict: out[e] = dot(z[a], fw[0:16]) + dot(z[b], fw[16:32]) + fc_b
__global__ void k_predict(const int* __restrict__ la,
                          const int* __restrict__ lb,
                          const float* __restrict__ fc_w,
                          const float* __restrict__ fc_b,
                          float* __restrict__ out) {
    __shared__ float fw[32];
    __shared__ float fb;
    if (threadIdx.x < 32) fw[threadIdx.x] = fc_w[threadIdx.x];
    if (threadIdx.x == 0) fb = fc_b[0];
    __syncthreads();

    int e = blockIdx.x * blockDim.x + threadIdx.x;
    if (e >= N_LABEL) return;

    int a = la[e], b = lb[e];
    const float4* za = (const float4*)(g_z + (size_t)a * FDIM);
    const float4* zb = (const float4*)(g_z + (size_t)b * FDIM);
    float acc = fb;
    #pragma unroll
    for (int q = 0; q < 4; q++) {
        float4 v = za[q];
        acc = fmaf(v.x, fw[4*q+0], acc);
        acc = fmaf(v.y, fw[4*q+1], acc);
        acc = fmaf(v.z, fw[4*q+2], acc);
        acc = fmaf(v.w, fw[4*q+3], acc);
    }
    #pragma unroll
    for (int q = 0; q < 4; q++) {
        float4 v = zb[q];
        acc = fmaf(v.x, fw[FDIM+4*q+0], acc);
        acc = fmaf(v.y, fw[FDIM+4*q+1], acc);
        acc = fmaf(v.z, fw[FDIM+4*q+2], acc);
        acc = fmaf(v.w, fw[FDIM+4*q+3], acc);
    }
    out[e] = acc;
}

// ---------------------------------------------------------------------------
extern "C" void kernel_launch(void* const* d_in, const int* in_sizes, int n_in,
                              void* d_out, int out_size) {
    const int*   x     = (const int*)  d_in[0];
    const int*   ei    = (const int*)  d_in[1];   // [2, E] row-major
    const int*   eli   = (const int*)  d_in[2];   // [2, EL]
    const float* embed = (const float*)d_in[3];
    const float* W1    = (const float*)d_in[4];
    const float* b1    = (const float*)d_in[5];
    const float* W2    = (const float*)d_in[6];
    const float* b2    = (const float*)d_in[7];
    const float* fc_w  = (const float*)d_in[8];
    const float* fc_b  = (const float*)d_in[9];
    float*       out   = (float*)d_out;

    const int* e_src = ei;
    const int* e_dst = ei + N_EDGES;
    const int* l_a   = eli;
    const int* l_b   = eli + N_LABEL;

    const int TB = 256;
    int gN = (N_NODES + TB - 1) / TB;
    int gE = (N_EDGES + TB - 1) / TB;
    int gL = (N_LABEL + TB - 1) / TB;
    int gG = N_NODES / 32;               // exact: 31250 blocks, 8 thr/node

    k_zero_deg  <<<gN, TB>>>();
    k_count     <<<gE, TB>>>(e_dst);
    k_scan1     <<<NB, 256>>>();
    k_scan2     <<<1, 512>>>();
    k_scan3     <<<gN, TB>>>();
    k_fill      <<<gE, TB>>>(e_src, e_dst);
    k_mm1       <<<gN, TB>>>(x, embed, W1);
    k_gather_mm2<<<gG, TB>>>(W2, b1);
    k_gather_z  <<<gG, TB>>>(b2);
    k_predict   <<<gL, TB>>>(l_a, l_b, fc_w, fc_b, out);
}

// round 4
// speedup vs baseline: 1.8524x; 1.1854x over previous
#include <cuda_runtime.h>
#include <cuda_fp16.h>
#include <cstdint>

#define N_NODES 1000000
#define N_EDGES 5000000
#define N_LABEL 2000000
#define FDIM    16

#define SCAN_CHUNK 2048
#define NB ((N_NODES + SCAN_CHUNK - 1) / SCAN_CHUNK)   // 489

// Scratch (device globals — allocation is forbidden)
__device__ int      g_deg [N_NODES];
__device__ int      g_off [N_NODES + 1];
__device__ int      g_cur [N_NODES];
__device__ int      g_csr [N_EDGES];
__device__ int      g_bsum[NB];
__device__ float    g_dinv[N_NODES];
__device__ unsigned g_msg1[N_NODES * 8];   // layer-1 messages, half2-packed
__device__ unsigned g_msg2[N_NODES * 8];   // layer-2 messages, half2-packed
__device__ float    g_z   [N_NODES * FDIM];

// ---------------------------------------------------------------------------
__global__ void k_zero_deg() {
    int i = blockIdx.x * blockDim.x + threadIdx.x;
    if (i < N_NODES) g_deg[i] = 0;
}

__global__ void k_count(const int* __restrict__ dst) {
    int e = blockIdx.x * blockDim.x + threadIdx.x;
    if (e < N_EDGES) atomicAdd(&g_deg[dst[e]], 1);
}

// dinv only needs deg — runs on the side stream, unblocks mm1 early.
__global__ void k_dinv() {
    int i = blockIdx.x * blockDim.x + threadIdx.x;
    if (i < N_NODES) g_dinv[i] = rsqrtf((float)(g_deg[i] + 1));  // +1 self loop
}

// ---------------------------------------------------------------------------
// 3-phase exclusive scan of g_deg into g_off.
__global__ void k_scan1() {
    __shared__ int s[256];
    int b = blockIdx.x, t = threadIdx.x;
    int base = b * SCAN_CHUNK + t * 8;
    int v[8], sum = 0;
    #pragma unroll
    for (int q = 0; q < 8; q++) {
        int idx = base + q;
        int d = (idx < N_NODES) ? g_deg[idx] : 0;
        v[q] = sum; sum += d;
    }
    s[t] = sum; __syncthreads();
    for (int o = 1; o < 256; o <<= 1) {
        int x = (t >= o) ? s[t - o] : 0;
        __syncthreads();
        s[t] += x;
        __syncthreads();
    }
    int excl = (t > 0) ? s[t - 1] : 0;
    #pragma unroll
    for (int q = 0; q < 8; q++) {
        int idx = base + q;
        if (idx < N_NODES) g_off[idx] = v[q] + excl;
    }
    if (t == 255) g_bsum[b] = s[255];
}

__global__ void k_scan2() {
    __shared__ int s[512];
    int t = threadIdx.x;
    s[t] = (t < NB) ? g_bsum[t] : 0;
    __syncthreads();
    for (int o = 1; o < 512; o <<= 1) {
        int x = (t >= o) ? s[t - o] : 0;
        __syncthreads();
        s[t] += x;
        __syncthreads();
    }
    if (t < NB) g_bsum[t] = (t > 0) ? s[t - 1] : 0;   // exclusive
}

__global__ void k_scan3() {
    int i = blockIdx.x * blockDim.x + threadIdx.x;
    if (i < N_NODES) {
        int o = g_off[i] + g_bsum[i >> 11];
        g_off[i] = o;
        g_cur[i] = o;
    }
    if (i == 0) g_off[N_NODES] = N_EDGES;
}

__global__ void k_fill(const int* __restrict__ src, const int* __restrict__ dst) {
    int e = blockIdx.x * blockDim.x + threadIdx.x;
    if (e >= N_EDGES) return;
    int pos = atomicAdd(&g_cur[dst[e]], 1);
    g_csr[pos] = src[e];
}

// ---------------------------------------------------------------------------
// K-mm1: msg1[i] = (embed[x[i]] @ W1) * dinv[i]  (half2-packed, 32 B/node)
__global__ void k_mm1(const int* __restrict__ x,
                      const float* __restrict__ embed,
                      const float* __restrict__ W1) {
    __shared__ float Ws[FDIM][FDIM];
    if (threadIdx.x < 256) {
        int k = threadIdx.x >> 4, j = threadIdx.x & 15;
        Ws[k][j] = W1[threadIdx.x];
    }
    __syncthreads();

    int i = blockIdx.x * blockDim.x + threadIdx.x;
    if (i >= N_NODES) return;

    const float4* rp = (const float4*)(embed + (size_t)x[i] * FDIM);
    float4 r0 = rp[0], r1 = rp[1], r2 = rp[2], r3 = rp[3];
    float row[FDIM] = {r0.x,r0.y,r0.z,r0.w, r1.x,r1.y,r1.z,r1.w,
                       r2.x,r2.y,r2.z,r2.w, r3.x,r3.y,r3.z,r3.w};
    float dv = g_dinv[i];
    float out[FDIM];
    #pragma unroll
    for (int j = 0; j < FDIM; j++) {
        float acc = 0.f;
        #pragma unroll
        for (int k = 0; k < FDIM; k++) acc = fmaf(row[k], Ws[k][j], acc);
        out[j] = acc * dv;
    }
    __half2 h[8];
    #pragma unroll
    for (int q = 0; q < 8; q++) h[q] = __floats2half2_rn(out[2*q], out[2*q+1]);
    uint4* mp = (uint4*)(g_msg1 + (size_t)i * 8);
    mp[0] = make_uint4(*(unsigned*)&h[0], *(unsigned*)&h[1], *(unsigned*)&h[2], *(unsigned*)&h[3]);
    mp[1] = make_uint4(*(unsigned*)&h[4], *(unsigned*)&h[5], *(unsigned*)&h[6], *(unsigned*)&h[7]);
}

// ---------------------------------------------------------------------------
// helper: accumulate one 8B (4 half) message chunk into float4
__device__ __forceinline__ void acc_h4(float4& a, uint2 m) {
    float2 f0 = __half22float2(*(__half2*)&m.x);
    float2 f1 = __half22float2(*(__half2*)&m.y);
    a.x += f0.x; a.y += f0.y; a.z += f1.x; a.w += f1.y;
}

// K-gather1 fused with layer-2 matmul. 4 threads/node, uint2 loads, 2-edge unroll.
// Grid exact: 1e6/64 blocks of 256 → full warps, shuffles safe.
__global__ void k_gather_mm2(const float* __restrict__ W2,
                             const float* __restrict__ b1) {
    __shared__ float Ws[FDIM][FDIM];
    __shared__ float bs[FDIM];
    if (threadIdx.x < 256) {
        int k = threadIdx.x >> 4, j = threadIdx.x & 15;
        Ws[k][j] = W2[threadIdx.x];
        if (threadIdx.x < FDIM) bs[threadIdx.x] = b1[threadIdx.x];
    }
    __syncthreads();

    int node  = blockIdx.x * 64 + (threadIdx.x >> 2);
    int t     = threadIdx.x & 3;
    int gbase = (threadIdx.x & 31) & ~3;

    int o0 = g_off[node], o1 = g_off[node + 1];
    const uint2* M = (const uint2*)g_msg1;

    float4 acc = make_float4(0.f, 0.f, 0.f, 0.f);
    acc_h4(acc, M[(size_t)node * 4 + t]);          // self message

    int j = o0;
    for (; j + 1 < o1; j += 2) {
        int sA = g_csr[j], sB = g_csr[j + 1];
        uint2 mA = M[(size_t)sA * 4 + t];
        uint2 mB = M[(size_t)sB * 4 + t];
        acc_h4(acc, mA);
        acc_h4(acc, mB);
    }
    if (j < o1) acc_h4(acc, M[(size_t)g_csr[j] * 4 + t]);

    float dv = g_dinv[node];
    float h[4];
    h[0] = fmaxf(fmaf(dv, acc.x, bs[4*t + 0]), 0.f);
    h[1] = fmaxf(fmaf(dv, acc.y, bs[4*t + 1]), 0.f);
    h[2] = fmaxf(fmaf(dv, acc.z, bs[4*t + 2]), 0.f);
    h[3] = fmaxf(fmaf(dv, acc.w, bs[4*t + 3]), 0.f);

    float o[4] = {0.f, 0.f, 0.f, 0.f};
    #pragma unroll
    for (int k = 0; k < FDIM; k++) {
        float hk = __shfl_sync(0xFFFFFFFFu, h[k & 3], gbase + (k >> 2));
        o[0] = fmaf(hk, Ws[k][4*t + 0], o[0]);
        o[1] = fmaf(hk, Ws[k][4*t + 1], o[1]);
        o[2] = fmaf(hk, Ws[k][4*t + 2], o[2]);
        o[3] = fmaf(hk, Ws[k][4*t + 3], o[3]);
    }
    __half2 p0 = __floats2half2_rn(o[0] * dv, o[1] * dv);
    __half2 p1 = __floats2half2_rn(o[2] * dv, o[3] * dv);
    ((uint2*)g_msg2)[(size_t)node * 4 + t] =
        make_uint2(*(unsigned*)&p0, *(unsigned*)&p1);
}

// K-gather2: z[i] = dinv[i] * (msg2[i] + Σ msg2[s]) + b2
__global__ void k_gather_z(const float* __restrict__ b2) {
    __shared__ float bs[FDIM];
    if (threadIdx.x < FDIM) bs[threadIdx.x] = b2[threadIdx.x];
    __syncthreads();

    int node = blockIdx.x * 64 + (threadIdx.x >> 2);
    int t    = threadIdx.x & 3;

    int o0 = g_off[node], o1 = g_off[node + 1];
    const uint2* M = (const uint2*)g_msg2;

    float4 acc = make_float4(0.f, 0.f, 0.f, 0.f);
    acc_h4(acc, M[(size_t)node * 4 + t]);

    int j = o0;
    for (; j + 1 < o1; j += 2) {
        int sA = g_csr[j], sB = g_csr[j + 1];
        uint2 mA = M[(size_t)sA * 4 + t];
        uint2 mB = M[(size_t)sB * 4 + t];
        acc_h4(acc, mA);
        acc_h4(acc, mB);
    }
    if (j < o1) acc_h4(acc, M[(size_t)g_csr[j] * 4 + t]);

    float dv = g_dinv[node];
    float4 zv = make_float4(fmaf(dv, acc.x, bs[4*t + 0]),
                            fmaf(dv, acc.y, bs[4*t + 1]),
                            fmaf(dv, acc.z, bs[4*t + 2]),
                            fmaf(dv, acc.w, bs[4*t + 3]));
    *(float4*)(g_z + (size_t)node * FDIM + 4*t) = zv;
}

// ---------------------------------------------------------------------------
__global__ void k_predict(const int* __restrict__ la,
                          const int* __restrict__ lb,
                          const float* __restrict__ fc_w,
                          const float* __restrict__ fc_b,
                          float* __restrict__ out) {
    __shared__ float fw[32];
    __shared__ float fb;
    if (threadIdx.x < 32) fw[threadIdx.x] = fc_w[threadIdx.x];
    if (threadIdx.x == 0) fb = fc_b[0];
    __syncthreads();

    int e = blockIdx.x * blockDim.x + threadIdx.x;
    if (e >= N_LABEL) return;

    int a = la[e], b = lb[e];
    const float4* za = (const float4*)(g_z + (size_t)a * FDIM);
    const float4* zb = (const float4*)(g_z + (size_t)b * FDIM);
    float acc = fb;
    #pragma unroll
    for (int q = 0; q < 4; q++) {
        float4 v = za[q];
        acc = fmaf(v.x, fw[4*q+0], acc);
        acc = fmaf(v.y, fw[4*q+1], acc);
        acc = fmaf(v.z, fw[4*q+2], acc);
        acc = fmaf(v.w, fw[4*q+3], acc);
    }
    #pragma unroll
    for (int q = 0; q < 4; q++) {
        float4 v = zb[q];
        acc = fmaf(v.x, fw[FDIM+4*q+0], acc);
        acc = fmaf(v.y, fw[FDIM+4*q+1], acc);
        acc = fmaf(v.z, fw[FDIM+4*q+2], acc);
        acc = fmaf(v.w, fw[FDIM+4*q+3], acc);
    }
    out[e] = acc;
}

// ---------------------------------------------------------------------------
extern "C" void kernel_launch(void* const* d_in, const int* in_sizes, int n_in,
                              void* d_out, int out_size) {
    const int*   x     = (const int*)  d_in[0];
    const int*   ei    = (const int*)  d_in[1];
    const int*   eli   = (const int*)  d_in[2];
    const float* embed = (const float*)d_in[3];
    const float* W1    = (const float*)d_in[4];
    const float* b1    = (const float*)d_in[5];
    const float* W2    = (const float*)d_in[6];
    const float* b2    = (const float*)d_in[7];
    const float* fc_w  = (const float*)d_in[8];
    const float* fc_b  = (const float*)d_in[9];
    float*       out   = (float*)d_out;

    const int* e_src = ei;
    const int* e_dst = ei + N_EDGES;
    const int* l_a   = eli;
    const int* l_b   = eli + N_LABEL;

    const int TB = 256;
    int gN = (N_NODES + TB - 1) / TB;
    int gE = (N_EDGES + TB - 1) / TB;
    int gL = (N_LABEL + TB - 1) / TB;
    int gG = N_NODES / 64;               // exact: 15625 blocks, 4 thr/node

    // One-time side stream + events (host objects; identical captured work
    // every call; graph deps come from the event record/wait pairs).
    static cudaStream_t s2 = nullptr;
    static cudaEvent_t  e1 = nullptr, e2 = nullptr;
    if (!s2) {
        if (cudaStreamCreateWithFlags(&s2, cudaStreamNonBlocking) != cudaSuccess) s2 = nullptr;
        cudaEventCreateWithFlags(&e1, cudaEventDisableTiming);
        cudaEventCreateWithFlags(&e2, cudaEventDisableTiming);
    }

    k_zero_deg<<<gN, TB>>>();
    k_count   <<<gE, TB>>>(e_dst);

    if (s2) {
        cudaEventRecord(e1, 0);
        cudaStreamWaitEvent(s2, e1, 0);
        // side stream: dinv -> mm1 (independent of scan/fill)
        k_dinv<<<gN, TB, 0, s2>>>();
        k_mm1 <<<gN, TB, 0, s2>>>(x, embed, W1);
        cudaEventRecord(e2, s2);
        // main stream: CSR build
        k_scan1<<<NB, 256>>>();
        k_scan2<<<1, 512>>>();
        k_scan3<<<gN, TB>>>();
        k_fill <<<gE, TB>>>(e_src, e_dst);
        cudaStreamWaitEvent(0, e2, 0);
    } else {
        k_dinv <<<gN, TB>>>();
        k_scan1<<<NB, 256>>>();
        k_scan2<<<1, 512>>>();
        k_scan3<<<gN, TB>>>();
        k_fill <<<gE, TB>>>(e_src, e_dst);
        k_mm1  <<<gN, TB>>>(x, embed, W1);
    }

    k_gather_mm2<<<gG, TB>>>(W2, b1);
    k_gather_z  <<<gG, TB>>>(b2);
    k_predict   <<<gL, TB>>>(l_a, l_b, fc_w, fc_b, out);
}

// round 5
// speedup vs baseline: 1.8996x; 1.0255x over previous
#include <cuda_runtime.h>
#include <cuda_fp16.h>
#include <cstdint>

#define N_NODES 1000000
#define N_EDGES 5000000
#define N_LABEL 2000000
#define FDIM    16

#define SCAN_CHUNK 2048
#define NB ((N_NODES + SCAN_CHUNK - 1) / SCAN_CHUNK)   // 489

// Scratch (device globals — allocation is forbidden)
__device__ int      g_deg [N_NODES];
__device__ int      g_off [N_NODES + 1];
__device__ int      g_cur [N_NODES];
__device__ int      g_csr [N_EDGES];
__device__ int      g_bsum[NB];
__device__ float    g_dinv[N_NODES];
__device__ unsigned g_msg1[N_NODES * 8];   // layer-1 messages, half2-packed
__device__ unsigned g_msg2[N_NODES * 8];   // layer-2 messages, half2-packed
__device__ unsigned g_zh  [N_NODES * 8];   // final z, half2-packed (32 B/row)

// ---------------------------------------------------------------------------
__global__ void k_zero_deg() {
    int i = blockIdx.x * blockDim.x + threadIdx.x;
    if (i < N_NODES) g_deg[i] = 0;
}

// E % 4 == 0: int4-vectorized degree count
__global__ void k_count(const int4* __restrict__ dst4) {
    int e = blockIdx.x * blockDim.x + threadIdx.x;
    if (e < N_EDGES / 4) {
        int4 d = dst4[e];
        atomicAdd(&g_deg[d.x], 1);
        atomicAdd(&g_deg[d.y], 1);
        atomicAdd(&g_deg[d.z], 1);
        atomicAdd(&g_deg[d.w], 1);
    }
}

// dinv only needs deg — runs on the side stream, unblocks mm1 early.
__global__ void k_dinv() {
    int i = blockIdx.x * blockDim.x + threadIdx.x;
    if (i < N_NODES) g_dinv[i] = rsqrtf((float)(g_deg[i] + 1));  // +1 self loop
}

// ---------------------------------------------------------------------------
// 3-phase exclusive scan of g_deg into g_off.
__global__ void k_scan1() {
    __shared__ int s[256];
    int b = blockIdx.x, t = threadIdx.x;
    int base = b * SCAN_CHUNK + t * 8;
    int v[8], sum = 0;
    #pragma unroll
    for (int q = 0; q < 8; q++) {
        int idx = base + q;
        int d = (idx < N_NODES) ? g_deg[idx] : 0;
        v[q] = sum; sum += d;
    }
    s[t] = sum; __syncthreads();
    for (int o = 1; o < 256; o <<= 1) {
        int x = (t >= o) ? s[t - o] : 0;
        __syncthreads();
        s[t] += x;
        __syncthreads();
    }
    int excl = (t > 0) ? s[t - 1] : 0;
    #pragma unroll
    for (int q = 0; q < 8; q++) {
        int idx = base + q;
        if (idx < N_NODES) g_off[idx] = v[q] + excl;
    }
    if (t == 255) g_bsum[b] = s[255];
}

__global__ void k_scan2() {
    __shared__ int s[512];
    int t = threadIdx.x;
    s[t] = (t < NB) ? g_bsum[t] : 0;
    __syncthreads();
    for (int o = 1; o < 512; o <<= 1) {
        int x = (t >= o) ? s[t - o] : 0;
        __syncthreads();
        s[t] += x;
        __syncthreads();
    }
    if (t < NB) g_bsum[t] = (t > 0) ? s[t - 1] : 0;   // exclusive
}

__global__ void k_scan3() {
    int i = blockIdx.x * blockDim.x + threadIdx.x;
    if (i < N_NODES) {
        int o = g_off[i] + g_bsum[i >> 11];
        g_off[i] = o;
        g_cur[i] = o;
    }
    if (i == 0) g_off[N_NODES] = N_EDGES;
}

// int4-vectorized CSR fill
__global__ void k_fill(const int4* __restrict__ src4, const int4* __restrict__ dst4) {
    int e = blockIdx.x * blockDim.x + threadIdx.x;
    if (e >= N_EDGES / 4) return;
    int4 s = src4[e];
    int4 d = dst4[e];
    g_csr[atomicAdd(&g_cur[d.x], 1)] = s.x;
    g_csr[atomicAdd(&g_cur[d.y], 1)] = s.y;
    g_csr[atomicAdd(&g_cur[d.z], 1)] = s.z;
    g_csr[atomicAdd(&g_cur[d.w], 1)] = s.w;
}

// ---------------------------------------------------------------------------
// K-mm1: msg1[i] = (embed[x[i]] @ W1) * dinv[i]  (half2-packed, 32 B/node)
__global__ void k_mm1(const int* __restrict__ x,
                      const float* __restrict__ embed,
                      const float* __restrict__ W1) {
    __shared__ float Ws[FDIM][FDIM];
    if (threadIdx.x < 256) {
        int k = threadIdx.x >> 4, j = threadIdx.x & 15;
        Ws[k][j] = W1[threadIdx.x];
    }
    __syncthreads();

    int i = blockIdx.x * blockDim.x + threadIdx.x;
    if (i >= N_NODES) return;

    const float4* rp = (const float4*)(embed + (size_t)x[i] * FDIM);
    float4 r0 = rp[0], r1 = rp[1], r2 = rp[2], r3 = rp[3];
    float row[FDIM] = {r0.x,r0.y,r0.z,r0.w, r1.x,r1.y,r1.z,r1.w,
                       r2.x,r2.y,r2.z,r2.w, r3.x,r3.y,r3.z,r3.w};
    float dv = g_dinv[i];
    float out[FDIM];
    #pragma unroll
    for (int j = 0; j < FDIM; j++) {
        float acc = 0.f;
        #pragma unroll
        for (int k = 0; k < FDIM; k++) acc = fmaf(row[k], Ws[k][j], acc);
        out[j] = acc * dv;
    }
    __half2 h[8];
    #pragma unroll
    for (int q = 0; q < 8; q++) h[q] = __floats2half2_rn(out[2*q], out[2*q+1]);
    uint4* mp = (uint4*)(g_msg1 + (size_t)i * 8);
    mp[0] = make_uint4(*(unsigned*)&h[0], *(unsigned*)&h[1], *(unsigned*)&h[2], *(unsigned*)&h[3]);
    mp[1] = make_uint4(*(unsigned*)&h[4], *(unsigned*)&h[5], *(unsigned*)&h[6], *(unsigned*)&h[7]);
}

// ---------------------------------------------------------------------------
__device__ __forceinline__ void acc_h4(float4& a, uint2 m) {
    float2 f0 = __half22float2(*(__half2*)&m.x);
    float2 f1 = __half22float2(*(__half2*)&m.y);
    a.x += f0.x; a.y += f0.y; a.z += f1.x; a.w += f1.y;
}

// Shared gather core: 4 threads/node, uint2 loads, 4-edge unroll.
__device__ __forceinline__ float4 gather_acc(const uint2* __restrict__ M,
                                             int node, int t, int o0, int o1) {
    float4 acc = make_float4(0.f, 0.f, 0.f, 0.f);
    acc_h4(acc, M[(size_t)node * 4 + t]);          // self message

    int j = o0;
    for (; j + 3 < o1; j += 4) {
        int s0 = g_csr[j],     s1 = g_csr[j + 1];
        int s2 = g_csr[j + 2], s3 = g_csr[j + 3];
        uint2 m0 = M[(size_t)s0 * 4 + t];
        uint2 m1 = M[(size_t)s1 * 4 + t];
        uint2 m2 = M[(size_t)s2 * 4 + t];
        uint2 m3 = M[(size_t)s3 * 4 + t];
        acc_h4(acc, m0); acc_h4(acc, m1);
        acc_h4(acc, m2); acc_h4(acc, m3);
    }
    for (; j < o1; j++) acc_h4(acc, M[(size_t)g_csr[j] * 4 + t]);
    return acc;
}

// K-gather1 fused with layer-2 matmul. Grid exact: 1e6/64 blocks — full warps.
__global__ void k_gather_mm2(const float* __restrict__ W2,
                             const float* __restrict__ b1) {
    __shared__ float Ws[FDIM][FDIM];
    __shared__ float bs[FDIM];
    if (threadIdx.x < 256) {
        int k = threadIdx.x >> 4, j = threadIdx.x & 15;
        Ws[k][j] = W2[threadIdx.x];
        if (threadIdx.x < FDIM) bs[threadIdx.x] = b1[threadIdx.x];
    }
    __syncthreads();

    int node  = blockIdx.x * 64 + (threadIdx.x >> 2);
    int t     = threadIdx.x & 3;
    int gbase = (threadIdx.x & 31) & ~3;

    float4 acc = gather_acc((const uint2*)g_msg1, node, t,
                            g_off[node], g_off[node + 1]);

    float dv = g_dinv[node];
    float h[4];
    h[0] = fmaxf(fmaf(dv, acc.x, bs[4*t + 0]), 0.f);
    h[1] = fmaxf(fmaf(dv, acc.y, bs[4*t + 1]), 0.f);
    h[2] = fmaxf(fmaf(dv, acc.z, bs[4*t + 2]), 0.f);
    h[3] = fmaxf(fmaf(dv, acc.w, bs[4*t + 3]), 0.f);

    float o[4] = {0.f, 0.f, 0.f, 0.f};
    #pragma unroll
    for (int k = 0; k < FDIM; k++) {
        float hk = __shfl_sync(0xFFFFFFFFu, h[k & 3], gbase + (k >> 2));
        o[0] = fmaf(hk, Ws[k][4*t + 0], o[0]);
        o[1] = fmaf(hk, Ws[k][4*t + 1], o[1]);
        o[2] = fmaf(hk, Ws[k][4*t + 2], o[2]);
        o[3] = fmaf(hk, Ws[k][4*t + 3], o[3]);
    }
    __half2 p0 = __floats2half2_rn(o[0] * dv, o[1] * dv);
    __half2 p1 = __floats2half2_rn(o[2] * dv, o[3] * dv);
    ((uint2*)g_msg2)[(size_t)node * 4 + t] =
        make_uint2(*(unsigned*)&p0, *(unsigned*)&p1);
}

// K-gather2: z[i] = dinv[i] * (msg2[i] + Σ msg2[s]) + b2   → half-packed g_zh
__global__ void k_gather_z(const float* __restrict__ b2) {
    __shared__ float bs[FDIM];
    if (threadIdx.x < FDIM) bs[threadIdx.x] = b2[threadIdx.x];
    __syncthreads();

    int node = blockIdx.x * 64 + (threadIdx.x >> 2);
    int t    = threadIdx.x & 3;

    float4 acc = gather_acc((const uint2*)g_msg2, node, t,
                            g_off[node], g_off[node + 1]);

    float dv = g_dinv[node];
    __half2 p0 = __floats2half2_rn(fmaf(dv, acc.x, bs[4*t + 0]),
                                   fmaf(dv, acc.y, bs[4*t + 1]));
    __half2 p1 = __floats2half2_rn(fmaf(dv, acc.z, bs[4*t + 2]),
                                   fmaf(dv, acc.w, bs[4*t + 3]));
    ((uint2*)g_zh)[(size_t)node * 4 + t] =
        make_uint2(*(unsigned*)&p0, *(unsigned*)&p1);
}

// ---------------------------------------------------------------------------
// K-predict: out[e] = dot(z[a], fw[0:16]) + dot(z[b], fw[16:32]) + fc_b
// z rows are half-packed, 32 B (= 2×uint4) each.
__device__ __forceinline__ float dot16h(uint4 m0, uint4 m1, const float* fw) {
    float acc = 0.f;
    const unsigned* u = &m0.x;
    #pragma unroll
    for (int q = 0; q < 4; q++) {
        float2 f = __half22float2(*(__half2*)&u[q]);
        acc = fmaf(f.x, fw[2*q],     acc);
        acc = fmaf(f.y, fw[2*q + 1], acc);
    }
    const unsigned* v = &m1.x;
    #pragma unroll
    for (int q = 0; q < 4; q++) {
        float2 f = __half22float2(*(__half2*)&v[q]);
        acc = fmaf(f.x, fw[8 + 2*q],     acc);
        acc = fmaf(f.y, fw[8 + 2*q + 1], acc);
    }
    return acc;
}

__global__ void k_predict(const int* __restrict__ la,
                          const int* __restrict__ lb,
                          const float* __restrict__ fc_w,
                          const float* __restrict__ fc_b,
                          float* __restrict__ out) {
    __shared__ float fw[32];
    __shared__ float fb;
    if (threadIdx.x < 32) fw[threadIdx.x] = fc_w[threadIdx.x];
    if (threadIdx.x == 0) fb = fc_b[0];
    __syncthreads();

    int e = blockIdx.x * blockDim.x + threadIdx.x;
    if (e >= N_LABEL) return;

    int a = la[e], b = lb[e];
    const uint4* za = (const uint4*)(g_zh + (size_t)a * 8);
    const uint4* zb = (const uint4*)(g_zh + (size_t)b * 8);
    uint4 a0 = za[0], a1 = za[1];
    uint4 b0 = zb[0], b1 = zb[1];

    float acc = fb + dot16h(a0, a1, fw) + dot16h(b0, b1, fw + FDIM);
    out[e] = acc;
}

// ---------------------------------------------------------------------------
extern "C" void kernel_launch(void* const* d_in, const int* in_sizes, int n_in,
                              void* d_out, int out_size) {
    const int*   x     = (const int*)  d_in[0];
    const int*   ei    = (const int*)  d_in[1];
    const int*   eli   = (const int*)  d_in[2];
    const float* embed = (const float*)d_in[3];
    const float* W1    = (const float*)d_in[4];
    const float* b1    = (const float*)d_in[5];
    const float* W2    = (const float*)d_in[6];
    const float* b2    = (const float*)d_in[7];
    const float* fc_w  = (const float*)d_in[8];
    const float* fc_b  = (const float*)d_in[9];
    float*       out   = (float*)d_out;

    const int4* e_src4 = (const int4*)ei;
    const int4* e_dst4 = (const int4*)(ei + N_EDGES);
    const int*  l_a    = eli;
    const int*  l_b    = eli + N_LABEL;

    const int TB = 256;
    int gN  = (N_NODES + TB - 1) / TB;
    int gE4 = (N_EDGES / 4 + TB - 1) / TB;
    int gL  = (N_LABEL + TB - 1) / TB;
    int gG  = N_NODES / 64;              // exact: 15625 blocks, 4 thr/node

    static cudaStream_t s2 = nullptr;
    static cudaEvent_t  e1 = nullptr, e2 = nullptr;
    if (!s2) {
        if (cudaStreamCreateWithFlags(&s2, cudaStreamNonBlocking) != cudaSuccess) s2 = nullptr;
        cudaEventCreateWithFlags(&e1, cudaEventDisableTiming);
        cudaEventCreateWithFlags(&e2, cudaEventDisableTiming);
    }

    k_zero_deg<<<gN, TB>>>();
    k_count   <<<gE4, TB>>>(e_dst4);

    if (s2) {
        cudaEventRecord(e1, 0);
        cudaStreamWaitEvent(s2, e1, 0);
        k_dinv<<<gN, TB, 0, s2>>>();
        k_mm1 <<<gN, TB, 0, s2>>>(x, embed, W1);
        cudaEventRecord(e2, s2);
        k_scan1<<<NB, 256>>>();
        k_scan2<<<1, 512>>>();
        k_scan3<<<gN, TB>>>();
        k_fill <<<gE4, TB>>>(e_src4, e_dst4);
        cudaStreamWaitEvent(0, e2, 0);
    } else {
        k_dinv <<<gN, TB>>>();
        k_scan1<<<NB, 256>>>();
        k_scan2<<<1, 512>>>();
        k_scan3<<<gN, TB>>>();
        k_fill <<<gE4, TB>>>(e_src4, e_dst4);
        k_mm1  <<<gN, TB>>>(x, embed, W1);
    }

    k_gather_mm2<<<gG, TB>>>(W2, b1);
    k_gather_z  <<<gG, TB>>>(b2);
    k_predict   <<<gL, TB>>>(l_a, l_b, fc_w, fc_b, out);
}

// round 6
// speedup vs baseline: 2.0754x; 1.0925x over previous
#include <cuda_runtime.h>
#include <cuda_fp16.h>
#include <cstdint>

#define N_NODES 1000000
#define N_EDGES 5000000
#define N_LABEL 2000000
#define FDIM    16

#define SCAN_CHUNK 2048
#define NB ((N_NODES + SCAN_CHUNK - 1) / SCAN_CHUNK)   // 489

// Scratch (device globals — allocation is forbidden)
__device__ int      g_deg [N_NODES];
__device__ int      g_off [N_NODES + 1];
__device__ int      g_cur [N_NODES];
__device__ int      g_csr [N_EDGES];
__device__ int      g_bsum[NB];
__device__ float    g_dinv[N_NODES];
__device__ unsigned g_msg1[N_NODES * 8];   // layer-1 messages, half2-packed
__device__ unsigned g_msg2[N_NODES * 8];   // layer-2 messages, half2-packed
__device__ float    g_pA  [N_NODES];       // dot(z_i, fc_w[0:16])
__device__ float    g_pB  [N_NODES];       // dot(z_i, fc_w[16:32])

// ---------------------------------------------------------------------------
// E % 4 == 0: int4-vectorized degree count
__global__ void k_count(const int4* __restrict__ dst4) {
    int e = blockIdx.x * blockDim.x + threadIdx.x;
    if (e < N_EDGES / 4) {
        int4 d = dst4[e];
        atomicAdd(&g_deg[d.x], 1);
        atomicAdd(&g_deg[d.y], 1);
        atomicAdd(&g_deg[d.z], 1);
        atomicAdd(&g_deg[d.w], 1);
    }
}

// dinv only needs deg — runs on the side stream, unblocks mm1 early.
__global__ void k_dinv() {
    int i = blockIdx.x * blockDim.x + threadIdx.x;
    if (i < N_NODES) g_dinv[i] = rsqrtf((float)(g_deg[i] + 1));  // +1 self loop
}

// ---------------------------------------------------------------------------
// 3-phase exclusive scan of g_deg into g_off.
__global__ void k_scan1() {
    __shared__ int s[256];
    int b = blockIdx.x, t = threadIdx.x;
    int base = b * SCAN_CHUNK + t * 8;
    int v[8], sum = 0;
    #pragma unroll
    for (int q = 0; q < 8; q++) {
        int idx = base + q;
        int d = (idx < N_NODES) ? g_deg[idx] : 0;
        v[q] = sum; sum += d;
    }
    s[t] = sum; __syncthreads();
    for (int o = 1; o < 256; o <<= 1) {
        int x = (t >= o) ? s[t - o] : 0;
        __syncthreads();
        s[t] += x;
        __syncthreads();
    }
    int excl = (t > 0) ? s[t - 1] : 0;
    #pragma unroll
    for (int q = 0; q < 8; q++) {
        int idx = base + q;
        if (idx < N_NODES) g_off[idx] = v[q] + excl;
    }
    if (t == 255) g_bsum[b] = s[255];
}

__global__ void k_scan2() {
    __shared__ int s[512];
    int t = threadIdx.x;
    s[t] = (t < NB) ? g_bsum[t] : 0;
    __syncthreads();
    for (int o = 1; o < 512; o <<= 1) {
        int x = (t >= o) ? s[t - o] : 0;
        __syncthreads();
        s[t] += x;
        __syncthreads();
    }
    if (t < NB) g_bsum[t] = (t > 0) ? s[t - 1] : 0;   // exclusive
}

__global__ void k_scan3() {
    int i = blockIdx.x * blockDim.x + threadIdx.x;
    if (i < N_NODES) {
        int o = g_off[i] + g_bsum[i >> 11];
        g_off[i] = o;
        g_cur[i] = o;
    }
    if (i == 0) g_off[N_NODES] = N_EDGES;
}

// int4-vectorized CSR fill
__global__ void k_fill(const int4* __restrict__ src4, const int4* __restrict__ dst4) {
    int e = blockIdx.x * blockDim.x + threadIdx.x;
    if (e >= N_EDGES / 4) return;
    int4 s = src4[e];
    int4 d = dst4[e];
    g_csr[atomicAdd(&g_cur[d.x], 1)] = s.x;
    g_csr[atomicAdd(&g_cur[d.y], 1)] = s.y;
    g_csr[atomicAdd(&g_cur[d.z], 1)] = s.z;
    g_csr[atomicAdd(&g_cur[d.w], 1)] = s.w;
}

// ---------------------------------------------------------------------------
// K-mm1: msg1[i] = (embed[x[i]] @ W1) * dinv[i]  (half2-packed, 32 B/node)
__global__ void k_mm1(const int* __restrict__ x,
                      const float* __restrict__ embed,
                      const float* __restrict__ W1) {
    __shared__ float Ws[FDIM][FDIM];
    if (threadIdx.x < 256) {
        int k = threadIdx.x >> 4, j = threadIdx.x & 15;
        Ws[k][j] = W1[threadIdx.x];
    }
    __syncthreads();

    int i = blockIdx.x * blockDim.x + threadIdx.x;
    if (i >= N_NODES) return;

    const float4* rp = (const float4*)(embed + (size_t)x[i] * FDIM);
    float4 r0 = rp[0], r1 = rp[1], r2 = rp[2], r3 = rp[3];
    float row[FDIM] = {r0.x,r0.y,r0.z,r0.w, r1.x,r1.y,r1.z,r1.w,
                       r2.x,r2.y,r2.z,r2.w, r3.x,r3.y,r3.z,r3.w};
    float dv = g_dinv[i];
    float out[FDIM];
    #pragma unroll
    for (int j = 0; j < FDIM; j++) {
        float acc = 0.f;
        #pragma unroll
        for (int k = 0; k < FDIM; k++) acc = fmaf(row[k], Ws[k][j], acc);
        out[j] = acc * dv;
    }
    __half2 h[8];
    #pragma unroll
    for (int q = 0; q < 8; q++) h[q] = __floats2half2_rn(out[2*q], out[2*q+1]);
    uint4* mp = (uint4*)(g_msg1 + (size_t)i * 8);
    mp[0] = make_uint4(*(unsigned*)&h[0], *(unsigned*)&h[1], *(unsigned*)&h[2], *(unsigned*)&h[3]);
    mp[1] = make_uint4(*(unsigned*)&h[4], *(unsigned*)&h[5], *(unsigned*)&h[6], *(unsigned*)&h[7]);
}

// ---------------------------------------------------------------------------
__device__ __forceinline__ void acc_h4(float4& a, uint2 m) {
    float2 f0 = __half22float2(*(__half2*)&m.x);
    float2 f1 = __half22float2(*(__half2*)&m.y);
    a.x += f0.x; a.y += f0.y; a.z += f1.x; a.w += f1.y;
}

// Gather core: 4 threads/node, uint2 loads, fully-batched groups of 4 with
// CLAMPED indices + predicated accumulate — no serial remainder chain.
__device__ __forceinline__ float4 gather_acc(const uint2* __restrict__ M,
                                             int node, int t, int o0, int o1) {
    float4 acc = make_float4(0.f, 0.f, 0.f, 0.f);
    acc_h4(acc, M[(size_t)node * 4 + t]);          // self message

    int last = o1 - 1;
    for (int j = o0; j < o1; j += 4) {
        int j1 = min(j + 1, last), j2 = min(j + 2, last), j3 = min(j + 3, last);
        int s0 = g_csr[j],  s1 = g_csr[j1];
        int s2 = g_csr[j2], s3 = g_csr[j3];
        uint2 m0 = M[(size_t)s0 * 4 + t];
        uint2 m1 = M[(size_t)s1 * 4 + t];
        uint2 m2 = M[(size_t)s2 * 4 + t];
        uint2 m3 = M[(size_t)s3 * 4 + t];
        acc_h4(acc, m0);
        if (j + 1 < o1) acc_h4(acc, m1);
        if (j + 2 < o1) acc_h4(acc, m2);
        if (j + 3 < o1) acc_h4(acc, m3);
    }
    return acc;
}

// K-gather1 fused with layer-2 matmul. Grid exact: 1e6/64 blocks — full warps.
__global__ void k_gather_mm2(const float* __restrict__ W2,
                             const float* __restrict__ b1) {
    __shared__ float Ws[FDIM][FDIM];
    __shared__ float bs[FDIM];
    if (threadIdx.x < 256) {
        int k = threadIdx.x >> 4, j = threadIdx.x & 15;
        Ws[k][j] = W2[threadIdx.x];
        if (threadIdx.x < FDIM) bs[threadIdx.x] = b1[threadIdx.x];
    }
    __syncthreads();

    int node  = blockIdx.x * 64 + (threadIdx.x >> 2);
    int t     = threadIdx.x & 3;
    int gbase = (threadIdx.x & 31) & ~3;

    float4 acc = gather_acc((const uint2*)g_msg1, node, t,
                            g_off[node], g_off[node + 1]);

    float dv = g_dinv[node];
    float h[4];
    h[0] = fmaxf(fmaf(dv, acc.x, bs[4*t + 0]), 0.f);
    h[1] = fmaxf(fmaf(dv, acc.y, bs[4*t + 1]), 0.f);
    h[2] = fmaxf(fmaf(dv, acc.z, bs[4*t + 2]), 0.f);
    h[3] = fmaxf(fmaf(dv, acc.w, bs[4*t + 3]), 0.f);

    float o[4] = {0.f, 0.f, 0.f, 0.f};
    #pragma unroll
    for (int k = 0; k < FDIM; k++) {
        float hk = __shfl_sync(0xFFFFFFFFu, h[k & 3], gbase + (k >> 2));
        o[0] = fmaf(hk, Ws[k][4*t + 0], o[0]);
        o[1] = fmaf(hk, Ws[k][4*t + 1], o[1]);
        o[2] = fmaf(hk, Ws[k][4*t + 2], o[2]);
        o[3] = fmaf(hk, Ws[k][4*t + 3], o[3]);
    }
    __half2 p0 = __floats2half2_rn(o[0] * dv, o[1] * dv);
    __half2 p1 = __floats2half2_rn(o[2] * dv, o[3] * dv);
    ((uint2*)g_msg2)[(size_t)node * 4 + t] =
        make_uint2(*(unsigned*)&p0, *(unsigned*)&p1);
}

// K-gather2 fused with final FC partials:
//   z = dinv*(msg2[i] + Σ msg2[s]) + b2
//   pA[i] = dot(z, fc_w[0:16]);  pB[i] = dot(z, fc_w[16:32])
__global__ void k_gather_z(const float* __restrict__ b2,
                           const float* __restrict__ fc_w) {
    __shared__ float bs[FDIM];
    __shared__ float fw[32];
    if (threadIdx.x < FDIM) bs[threadIdx.x] = b2[threadIdx.x];
    if (threadIdx.x < 32)   fw[threadIdx.x] = fc_w[threadIdx.x];
    __syncthreads();

    int node = blockIdx.x * 64 + (threadIdx.x >> 2);
    int t    = threadIdx.x & 3;

    float4 acc = gather_acc((const uint2*)g_msg2, node, t,
                            g_off[node], g_off[node + 1]);

    float dv = g_dinv[node];
    float z0 = fmaf(dv, acc.x, bs[4*t + 0]);
    float z1 = fmaf(dv, acc.y, bs[4*t + 1]);
    float z2 = fmaf(dv, acc.z, bs[4*t + 2]);
    float z3 = fmaf(dv, acc.w, bs[4*t + 3]);

    float pa = z0 * fw[4*t] + z1 * fw[4*t+1] + z2 * fw[4*t+2] + z3 * fw[4*t+3];
    float pb = z0 * fw[16+4*t] + z1 * fw[16+4*t+1]
             + z2 * fw[16+4*t+2] + z3 * fw[16+4*t+3];

    // reduce across the 4-thread group (xor 1, 2 stay in-group)
    pa += __shfl_xor_sync(0xFFFFFFFFu, pa, 1);
    pa += __shfl_xor_sync(0xFFFFFFFFu, pa, 2);
    pb += __shfl_xor_sync(0xFFFFFFFFu, pb, 1);
    pb += __shfl_xor_sync(0xFFFFFFFFu, pb, 2);

    if (t == 0) {
        g_pA[node] = pa;
        g_pB[node] = pb;
    }
}

// ---------------------------------------------------------------------------
// K-predict: out[e] = pA[la[e]] + pB[lb[e]] + fc_b
__global__ void k_predict(const int* __restrict__ la,
                          const int* __restrict__ lb,
                          const float* __restrict__ fc_b,
                          float* __restrict__ out) {
    int e = blockIdx.x * blockDim.x + threadIdx.x;
    if (e >= N_LABEL) return;
    float fb = __ldg(fc_b);
    out[e] = g_pA[la[e]] + g_pB[lb[e]] + fb;
}

// ---------------------------------------------------------------------------
extern "C" void kernel_launch(void* const* d_in, const int* in_sizes, int n_in,
                              void* d_out, int out_size) {
    const int*   x     = (const int*)  d_in[0];
    const int*   ei    = (const int*)  d_in[1];
    const int*   eli   = (const int*)  d_in[2];
    const float* embed = (const float*)d_in[3];
    const float* W1    = (const float*)d_in[4];
    const float* b1    = (const float*)d_in[5];
    const float* W2    = (const float*)d_in[6];
    const float* b2    = (const float*)d_in[7];
    const float* fc_w  = (const float*)d_in[8];
    const float* fc_b  = (const float*)d_in[9];
    float*       out   = (float*)d_out;

    const int4* e_src4 = (const int4*)ei;
    const int4* e_dst4 = (const int4*)(ei + N_EDGES);
    const int*  l_a    = eli;
    const int*  l_b    = eli + N_LABEL;

    const int TB = 256;
    int gN  = (N_NODES + TB - 1) / TB;
    int gE4 = (N_EDGES / 4 + TB - 1) / TB;
    int gL  = (N_LABEL + TB - 1) / TB;
    int gG  = N_NODES / 64;              // exact: 15625 blocks, 4 thr/node

    static cudaStream_t s2 = nullptr;
    static cudaEvent_t  e1 = nullptr, e2 = nullptr;
    static void* degPtr = nullptr;
    if (!e1) {
        if (cudaStreamCreateWithFlags(&s2, cudaStreamNonBlocking) != cudaSuccess) s2 = nullptr;
        cudaEventCreateWithFlags(&e1, cudaEventDisableTiming);
        cudaEventCreateWithFlags(&e2, cudaEventDisableTiming);
        cudaGetSymbolAddress(&degPtr, g_deg);
    }

    cudaMemsetAsync(degPtr, 0, N_NODES * sizeof(int), 0);
    k_count<<<gE4, TB>>>(e_dst4);

    if (s2) {
        cudaEventRecord(e1, 0);
        cudaStreamWaitEvent(s2, e1, 0);
        k_dinv<<<gN, TB, 0, s2>>>();
        k_mm1 <<<gN, TB, 0, s2>>>(x, embed, W1);
        cudaEventRecord(e2, s2);
        k_scan1<<<NB, 256>>>();
        k_scan2<<<1, 512>>>();
        k_scan3<<<gN, TB>>>();
        k_fill <<<gE4, TB>>>(e_src4, e_dst4);
        cudaStreamWaitEvent(0, e2, 0);
    } else {
        k_dinv <<<gN, TB>>>();
        k_scan1<<<NB, 256>>>();
        k_scan2<<<1, 512>>>();
        k_scan3<<<gN, TB>>>();
        k_fill <<<gE4, TB>>>(e_src4, e_dst4);
        k_mm1  <<<gN, TB>>>(x, embed, W1);
    }

    k_gather_mm2<<<gG, TB>>>(W2, b1);
    k_gather_z  <<<gG, TB>>>(b2, fc_w);
    k_predict   <<<gL, TB>>>(l_a, l_b, fc_b, out);
}